// round 15
// baseline (speedup 1.0000x reference)
#include <cuda_runtime.h>
#include <cuda_bf16.h>
#include <cstdint>
#include <cstddef>

// ---------------- problem constants ----------------
static constexpr int Bc = 16;
static constexpr int Dc = 512;
static constexpr int Tc = 1500;
static constexpr int Nc = Bc * Tc;              // 24000
static constexpr int Kc = 4096;
static constexpr int ROWB = 128;                // CTA row tile
static constexpr int COLB = 128;                // CTA col tile
static constexpr int NRB  = (Nc + ROWB - 1) / ROWB;   // 188
static constexpr int NPAD = NRB * ROWB;         // 24064
static constexpr int NCB  = Kc / COLB;          // 32
static constexpr int NKCH = 8;                  // 512 / 64
static constexpr int CPB    = 20;               // chunks per batch
static constexpr int RCHUNK = Tc / CPB;         // 75 rows, batch-aligned
static constexpr int NCHUNKS = Bc * CPB;        // 320
static constexpr int STAGE = 32768;             // A 16KB + B 16KB per stage
static constexpr int NSTG  = 3;                 // 3-stage pipeline
static constexpr int SMEM_BYTES = NSTG * STAGE; // 98304; 2 CTAs/SM
static constexpr int GT = 128;                  // GEMM threads/CTA (4 warps)
static constexpr int TTILES = 47;               // ceil(1500/32)
static constexpr int PREP_BLKS = TTILES * Bc;   // 752

// ---------------- device scratch ----------------
// Device globals are zero-initialized at load; g_zt pad rows (Nc..NPAD) are
// never written and stay zero. Masked-row tiles of g_zt may hold stale values
// across graph replays: inputs are identical per replay, and masked rows'
// GEMM results are discarded in the epilogue, so output stays deterministic.
__device__ __nv_bfloat16 g_w[(size_t)NPAD * Kc];     // exp(-dist) numerators
__device__ __nv_bfloat16 g_zt[(size_t)NPAD * Dc];    // -2*z bf16 [N][512]
__device__ __nv_bfloat16 g_cbt[(size_t)Kc * Dc];     // bf16 codebook [K][512]
__device__ float g_Z[Nc];
__device__ float g_z2[Nc];
__device__ float g_c2[Kc];
__device__ int   g_nvalid[Bc];
__device__ float g_cd[Kc];

// ---------------- helpers ----------------
__device__ __forceinline__ uint32_t smem_u32(const void* p) {
    uint32_t a;
    asm("{ .reg .u64 t; cvta.to.shared.u64 t, %1; cvt.u32.u64 %0, t; }" : "=r"(a) : "l"(p));
    return a;
}
__device__ __forceinline__ uint32_t swz(uint32_t off) { return off ^ ((off >> 3) & 0x70); }
__device__ __forceinline__ float fsqrt_ap(float x) {
    float r; asm("sqrt.approx.ftz.f32 %0, %1;" : "=f"(r) : "f"(x)); return r;
}
__device__ __forceinline__ float fex2_ap(float x) {
    float r; asm("ex2.approx.ftz.f32 %0, %1;" : "=f"(r) : "f"(x)); return r;
}
__device__ __forceinline__ float flg2_ap(float x) {
    float r; asm("lg2.approx.ftz.f32 %0, %1;" : "=f"(r) : "f"(x)); return r;
}

// shared dtype-sniffing nvalid computation (pure function of inputs)
__device__ __forceinline__ int compute_nvalid(const void* lenp, const void* stridep, int b) {
    long long s = 320;
    if (stridep) {
        long long v = *(const long long*)stridep;
        if (v > 0 && v < (1ll << 31)) s = v;
        else { int v32 = *(const int*)stridep; if (v32 > 0) s = v32; }
    }
    const long long* l64 = (const long long*)lenp;
    const int*       l32 = (const int*)lenp;
    bool is64 = true;
    for (int bb = 0; bb < Bc; bb++) {
        long long v = l64[bb];
        if (v < 0 || v >= (1ll << 31)) { is64 = false; break; }
    }
    long long L = is64 ? l64[b] : (long long)l32[b];
    long long nv = L / s;
    if (nv > Tc) nv = Tc;
    if (nv < 0) nv = 0;
    return (int)nv;
}

#define CP_ASYNC16(dst, src) \
    asm volatile("cp.async.cg.shared.global [%0], [%1], 16;" :: "r"(dst), "l"(src))
#define CP_COMMIT() asm volatile("cp.async.commit_group;")
#define CP_WAIT(n)  asm volatile("cp.async.wait_group %0;" :: "n"(n))

#define LDSM4(R, addr) \
    asm volatile("ldmatrix.sync.aligned.m8n8.x4.shared.b16 {%0,%1,%2,%3}, [%4];" \
        : "=r"((R)[0]), "=r"((R)[1]), "=r"((R)[2]), "=r"((R)[3]) : "r"(addr))

#define MMA_BF16(C, A, b0, b1) \
    asm volatile("mma.sync.aligned.m16n8k16.row.col.f32.bf16.bf16.f32 " \
        "{%0,%1,%2,%3}, {%4,%5,%6,%7}, {%8,%9}, {%0,%1,%2,%3};" \
        : "+f"((C)[0]), "+f"((C)[1]), "+f"((C)[2]), "+f"((C)[3]) \
        : "r"((A)[0]), "r"((A)[1]), "r"((A)[2]), "r"((A)[3]), "r"(b0), "r"(b1))

// ---------------- k_pre: fused prep(transpose+z2) / c2 / init, mask-skip ----------------
__global__ __launch_bounds__(256)
void k_pre(const float* __restrict__ feat, const float* __restrict__ cb,
           const void* lenp, const void* stridep) {
    const int blk = blockIdx.x;
    const int tid = threadIdx.x;
    if (blk < PREP_BLKS) {
        const int b  = blk / TTILES;
        const int t0 = (blk - b * TTILES) * 32;
        const int nv = compute_nvalid(lenp, stridep, b);
        if (t0 >= nv) return;   // mask-skip

        __shared__ uint32_t tile[32][257];
        __shared__ float sz[32];
        const int tx = tid & 31, ty = tid >> 5;
        if (tid < 32) sz[tid] = 0.f;
        __syncthreads();
        const int t = t0 + tx;
        const bool tval = t < Tc;
        const float* src = feat + (size_t)b * Dc * Tc + t;
        float ssq = 0.f;
        #pragma unroll 8
        for (int j = 0; j < 32; j++) {
            int d = (j * 8 + ty) * 2;
            float v0 = tval ? src[(size_t)d * Tc] : 0.f;
            float v1 = tval ? src[(size_t)(d + 1) * Tc] : 0.f;
            ssq += v0 * v0 + v1 * v1;
            __nv_bfloat162 p = __floats2bfloat162_rn(-2.f * v0, -2.f * v1);
            tile[tx][d >> 1] = *(uint32_t*)&p;
        }
        atomicAdd(&sz[tx], ssq);
        __syncthreads();
        if (ty == 0 && tval) g_z2[b * Tc + t] = sz[tx];
        uint32_t* dst = (uint32_t*)&g_zt[(size_t)(b * Tc + t0) * Dc];
        #pragma unroll
        for (int r = 0; r < 32; r++) {
            if (t0 + r < Tc) dst[r * 256 + tid] = tile[r][tid];
        }
    } else {
        const int cblk = blk - PREP_BLKS;    // 0..511
        int zi = cblk * 256 + tid;
        if (zi < Nc) g_Z[zi] = 0.f;
        if (zi < Kc) g_cd[zi] = 0.f;
        if (cblk == 0 && tid < Bc) {
            g_nvalid[tid] = compute_nvalid(lenp, stridep, tid);
        }
        const int code = cblk * 8 + (tid >> 5);
        const int lane = tid & 31;
        const float* r = cb + (size_t)code * Dc;
        __nv_bfloat16* w = g_cbt + (size_t)code * Dc;
        float s = 0.f;
        #pragma unroll
        for (int it = 0; it < 4; it++) {
            int d = it * 128 + lane * 4;
            float4 v = *(const float4*)(r + d);
            s += v.x * v.x + v.y * v.y + v.z * v.z + v.w * v.w;
            __nv_bfloat162 p0 = __floats2bfloat162_rn(v.x, v.y);
            __nv_bfloat162 p1 = __floats2bfloat162_rn(v.z, v.w);
            *(uint2*)(w + d) = make_uint2(*(uint32_t*)&p0, *(uint32_t*)&p1);
        }
        #pragma unroll
        for (int o = 16; o; o >>= 1) s += __shfl_down_sync(0xffffffffu, s, o);
        if (lane == 0) g_c2[code] = s;
    }
}

// ---------------- cp.async stage issue (128 threads) ----------------
__device__ __forceinline__ void issue_stage(uint32_t sb, int kc, int n0, int k0, int tid) {
    uint32_t sbase = sb + (uint32_t)(kc % NSTG) * STAGE;
    int kcol = kc * 64;
    #pragma unroll
    for (int i = 0; i < 8; i++) {          // A: 1024 x 16B
        int id = i * GT + tid;
        int row = id >> 3, ch = id & 7;
        const void* src = &g_zt[(size_t)(n0 + row) * Dc + kcol + ch * 8];
        uint32_t dst = sbase + swz((uint32_t)(row * 128 + ch * 16));
        CP_ASYNC16(dst, src);
    }
    #pragma unroll
    for (int i = 0; i < 8; i++) {          // B: 1024 x 16B
        int id = i * GT + tid;
        int row = id >> 3, ch = id & 7;
        const void* src = &g_cbt[(size_t)(k0 + row) * Dc + kcol + ch * 8];
        uint32_t dst = sbase + 16384u + swz((uint32_t)(row * 128 + ch * 16));
        CP_ASYNC16(dst, src);
    }
    CP_COMMIT();
}

// ---------------- bf16 mma GEMM + fused softmax-numerator epilogue ----------------
// CTA 128x128, 4 warps in 2x2. Warp tile 64x64 (8 LDSM4 -> 32 MMAs per ks).
// 3-stage cp.async; 128 threads -> 256-reg budget -> 2 CTAs/SM retained.
__global__ __launch_bounds__(GT, 2)
void k_gemm_mma() {
    extern __shared__ __align__(1024) char smem[];
    const uint32_t sb = smem_u32(smem);
    const int tid  = threadIdx.x;
    const int warp = tid >> 5;     // 0..3
    const int lane = tid & 31;
    const int k0 = blockIdx.x * COLB;
    const int n0 = blockIdx.y * ROWB;

    // sync-free CTA skip: valid rows are a prefix of each batch
    {
        int b0 = n0 / Tc, t0 = n0 - b0 * Tc;
        bool any = (t0 < g_nvalid[b0]);
        if (!any && (t0 + ROWB > Tc) && (b0 + 1 < Bc)) any = (g_nvalid[b0 + 1] > 0);
        if (!any) return;
    }

    issue_stage(sb, 0, n0, k0, tid);
    issue_stage(sb, 1, n0, k0, tid);

    const int wr = warp >> 1;      // 0..1 (64-row half)
    const int wc = warp & 1;       // 0..1 (64-col half)
    const int g  = lane >> 3;      // ldmatrix address group
    const int lr = lane & 7;

    uint32_t aoff[4], boff[4];
    {
        int arow  = wr * 64 + (g & 1) * 8 + lr;
        int acolb = (g >> 1) * 16;
        #pragma unroll
        for (int mt = 0; mt < 4; mt++)
            aoff[mt] = swz((uint32_t)((arow + mt * 16) * 128 + acolb));
        int bcolb = (g & 1) * 16;
        #pragma unroll
        for (int p = 0; p < 4; p++) {
            int brow = wc * 64 + p * 16 + (g >> 1) * 8 + lr;
            boff[p] = 16384u + swz((uint32_t)(brow * 128 + bcolb));
        }
    }

    float acc[4][8][4];
    #pragma unroll
    for (int mt = 0; mt < 4; mt++)
        #pragma unroll
        for (int nt = 0; nt < 8; nt++)
            #pragma unroll
            for (int q = 0; q < 4; q++) acc[mt][nt][q] = 0.f;

    #pragma unroll 1
    for (int kc = 0; kc < NKCH; kc++) {
        if (kc < NKCH - 1) { CP_WAIT(1); } else { CP_WAIT(0); }
        __syncthreads();   // publishes stage kc; proves compute kc-1 done
        if (kc + 2 < NKCH) issue_stage(sb, kc + 2, n0, k0, tid);
        uint32_t sbase = sb + (uint32_t)(kc % NSTG) * STAGE;
        #pragma unroll
        for (int ks = 0; ks < 4; ks++) {
            const uint32_t kx = (uint32_t)(ks * 32);   // swz(off+kx)==swz(off)^kx
            uint32_t A[4][4], B[4][4];
            #pragma unroll
            for (int mt = 0; mt < 4; mt++) LDSM4(A[mt], sbase + (aoff[mt] ^ kx));
            #pragma unroll
            for (int p = 0; p < 4; p++)    LDSM4(B[p],  sbase + (boff[p] ^ kx));
            #pragma unroll
            for (int mt = 0; mt < 4; mt++)
                #pragma unroll
                for (int nt = 0; nt < 8; nt++)
                    MMA_BF16(acc[mt][nt], A[mt], B[nt >> 1][(nt & 1) * 2], B[nt >> 1][(nt & 1) * 2 + 1]);
        }
    }

    // ---- fused epilogue: w = ex2(-log2e * sqrt(max(z2 + c2 + acc, 1e-12))) ----
    const float NLOG2E = -1.4426950408889634f;
    const int rowq = lane >> 2;
    const int colp = (lane & 3) * 2;
    #pragma unroll
    for (int mt = 0; mt < 4; mt++) {
        int r0 = n0 + wr * 64 + mt * 16 + rowq;
        int r1 = r0 + 8;
        int b0i = r0 / Tc, t0i = r0 - b0i * Tc;
        int b1i = r1 / Tc, t1i = r1 - b1i * Tc;
        bool v0 = (r0 < Nc) && (t0i < g_nvalid[b0i]);
        bool v1 = (r1 < Nc) && (t1i < g_nvalid[b1i]);
        float z20 = v0 ? g_z2[r0] : 0.f;
        float z21 = v1 ? g_z2[r1] : 0.f;
        float rs0 = 0.f, rs1 = 0.f;
        #pragma unroll
        for (int nt = 0; nt < 8; nt++) {
            int col = k0 + wc * 64 + nt * 8 + colp;
            float2 c2 = *(const float2*)&g_c2[col];
            if (v0) {
                float d2a = fmaxf(z20 + c2.x + acc[mt][nt][0], 1e-12f);
                float d2b = fmaxf(z20 + c2.y + acc[mt][nt][1], 1e-12f);
                float w0 = fex2_ap(NLOG2E * fsqrt_ap(d2a));
                float w1 = fex2_ap(NLOG2E * fsqrt_ap(d2b));
                rs0 += w0 + w1;
                __nv_bfloat162 pk = __floats2bfloat162_rn(w0, w1);
                *(__nv_bfloat162*)&g_w[(size_t)r0 * Kc + col] = pk;
            }
            if (v1) {
                float d2a = fmaxf(z21 + c2.x + acc[mt][nt][2], 1e-12f);
                float d2b = fmaxf(z21 + c2.y + acc[mt][nt][3], 1e-12f);
                float w0 = fex2_ap(NLOG2E * fsqrt_ap(d2a));
                float w1 = fex2_ap(NLOG2E * fsqrt_ap(d2b));
                rs1 += w0 + w1;
                __nv_bfloat162 pk = __floats2bfloat162_rn(w0, w1);
                *(__nv_bfloat162*)&g_w[(size_t)r1 * Kc + col] = pk;
            }
        }
        rs0 += __shfl_xor_sync(0xffffffffu, rs0, 1);
        rs0 += __shfl_xor_sync(0xffffffffu, rs0, 2);
        rs1 += __shfl_xor_sync(0xffffffffu, rs1, 1);
        rs1 += __shfl_xor_sync(0xffffffffu, rs1, 2);
        if ((lane & 3) == 0) {
            if (v0) atomicAdd(&g_Z[r0], rs0);
            if (v1) atomicAdd(&g_Z[r1], rs1);
        }
    }
}

// ---------------- column reduce: uint4 loads, fused cd atomics ----------------
__global__ void k_colreduce() {
    const int grp = blockIdx.x * blockDim.x + threadIdx.x;   // 0..511 (uint4 group)
    const int chunk = blockIdx.y;                             // 0..319
    const int b  = chunk / CPB;
    const int t0 = (chunk - b * CPB) * RCHUNK;
    const int nv = g_nvalid[b];
    int tend = nv - t0;
    if (tend <= 0) return;
    if (tend > RCHUNK) tend = RCHUNK;
    float acc[8];
    #pragma unroll
    for (int j = 0; j < 8; j++) acc[j] = 0.f;
    int n = b * Tc + t0;
    const char* base = (const char*)g_w + (size_t)n * Kc * 2 + grp * 16;
    #pragma unroll 4
    for (int i = 0; i < tend; i++, n++, base += Kc * 2) {
        uint4 v = *(const uint4*)base;
        float iz = __fdividef(1.f, g_Z[n]);
        float2 f0 = __bfloat1622float2(*(const __nv_bfloat162*)&v.x);
        float2 f1 = __bfloat1622float2(*(const __nv_bfloat162*)&v.y);
        float2 f2 = __bfloat1622float2(*(const __nv_bfloat162*)&v.z);
        float2 f3 = __bfloat1622float2(*(const __nv_bfloat162*)&v.w);
        acc[0] += f0.x * iz; acc[1] += f0.y * iz;
        acc[2] += f1.x * iz; acc[3] += f1.y * iz;
        acc[4] += f2.x * iz; acc[5] += f2.y * iz;
        acc[6] += f3.x * iz; acc[7] += f3.y * iz;
    }
    #pragma unroll
    for (int j = 0; j < 8; j++) atomicAdd(&g_cd[grp * 8 + j], acc[j]);
}

// ---------------- final entropy (reads 16KB g_cd) ----------------
__device__ __forceinline__ float blockSum(float v) {
    __shared__ float sh[32];
    int lane = threadIdx.x & 31, w = threadIdx.x >> 5;
    #pragma unroll
    for (int o = 16; o; o >>= 1) v += __shfl_down_sync(0xffffffffu, v, o);
    if (!lane) sh[w] = v;
    __syncthreads();
    float r = 0.f;
    if (w == 0) {
        r = (lane < (blockDim.x >> 5)) ? sh[lane] : 0.f;
        #pragma unroll
        for (int o = 16; o; o >>= 1) r += __shfl_down_sync(0xffffffffu, r, o);
        if (!lane) sh[0] = r;
    }
    __syncthreads();
    float out = sh[0];
    __syncthreads();
    return out;
}

__global__ void k_final(float* out) {
    const int tid = threadIdx.x;   // 1024
    const float LN2 = 0.6931471805599453f;
    float cd[4];
    #pragma unroll
    for (int j = 0; j < 4; j++) cd[j] = g_cd[tid + j * 1024];
    float tot = (cd[0] + cd[1]) + (cd[2] + cd[3]);
    float S = blockSum(tot);
    float denom = S + 1e-8f;
    float e = 0.f;
    #pragma unroll
    for (int j = 0; j < 4; j++) {
        float p = cd[j] / denom;
        e += p * (flg2_ap(p + 1e-8f) * LN2);   // log(x) = lg2(x)*ln2
    }
    float E = blockSum(e);
    if (tid == 0) out[0] = 1.f + E / (flg2_ap((float)Kc) * LN2);
}

// ---------------- launch ----------------
extern "C" void kernel_launch(void* const* d_in, const int* in_sizes, int n_in,
                              void* d_out, int out_size) {
    const float* feat = (const float*)d_in[0];
    const float* cb   = (const float*)d_in[1];
    const void*  lenp = d_in[2];
    const void*  stridep = (n_in > 3) ? d_in[3] : nullptr;

    cudaFuncSetAttribute(k_gemm_mma, cudaFuncAttributeMaxDynamicSharedMemorySize, SMEM_BYTES);

    k_pre<<<PREP_BLKS + Kc / 8, 256>>>(feat, cb, lenp, stridep);   // 1264 blocks

    dim3 gg(NCB, NRB);                       // 32 x 188
    k_gemm_mma<<<gg, GT, SMEM_BYTES>>>();

    dim3 gr(Kc / 2048, NCHUNKS);             // 2 x 320 (uint4 groups)
    k_colreduce<<<gr, 256>>>();
    k_final<<<1, 1024>>>((float*)d_out);
    (void)in_sizes; (void)out_size;
}

// round 16
// speedup vs baseline: 1.1196x; 1.1196x over previous
#include <cuda_runtime.h>
#include <cuda_bf16.h>
#include <cstdint>
#include <cstddef>

// ---------------- problem constants ----------------
static constexpr int Bc = 16;
static constexpr int Dc = 512;
static constexpr int Tc = 1500;
static constexpr int Nc = Bc * Tc;              // 24000
static constexpr int Kc = 4096;
static constexpr int ROWB = 128;                // CTA row tile
static constexpr int COLB = 128;                // CTA col tile
static constexpr int NRB  = (Nc + ROWB - 1) / ROWB;   // 188
static constexpr int NPAD = NRB * ROWB;         // 24064
static constexpr int NCB  = Kc / COLB;          // 32
static constexpr int NKCH = 8;                  // 512 / 64
static constexpr int CPB    = 20;               // chunks per batch (best)
static constexpr int RCHUNK = Tc / CPB;         // 75 rows, batch-aligned
static constexpr int NCHUNKS = Bc * CPB;        // 320
static constexpr int STAGE = 32768;             // A 16KB + B 16KB per stage
static constexpr int NSTG  = 3;                 // 3-stage pipeline
static constexpr int SMEM_BYTES = NSTG * STAGE; // 98304; 2 CTAs/SM
static constexpr int TTILES = 47;               // ceil(1500/32)
static constexpr int PREP_BLKS = TTILES * Bc;   // 752

// ---------------- device scratch ----------------
// Device globals are zero-initialized at load; g_zt pad rows (Nc..NPAD) are
// never written and stay zero. Masked-row tiles of g_zt may hold stale values
// across graph replays: inputs are identical per replay, and masked rows'
// GEMM results are discarded in the epilogue, so output stays deterministic.
__device__ __nv_bfloat16 g_w[(size_t)NPAD * Kc];     // exp(-dist) numerators
__device__ __nv_bfloat16 g_zt[(size_t)NPAD * Dc];    // -2*z bf16 [N][512]
__device__ __nv_bfloat16 g_cbt[(size_t)Kc * Dc];     // bf16 codebook [K][512]
__device__ float g_Z[Nc];
__device__ float g_z2[Nc];
__device__ float g_c2[Kc];
__device__ int   g_nvalid[Bc];
__device__ float g_cd[Kc];

// ---------------- helpers ----------------
__device__ __forceinline__ uint32_t smem_u32(const void* p) {
    uint32_t a;
    asm("{ .reg .u64 t; cvta.to.shared.u64 t, %1; cvt.u32.u64 %0, t; }" : "=r"(a) : "l"(p));
    return a;
}
__device__ __forceinline__ uint32_t swz(uint32_t off) { return off ^ ((off >> 3) & 0x70); }
__device__ __forceinline__ float fsqrt_ap(float x) {
    float r; asm("sqrt.approx.ftz.f32 %0, %1;" : "=f"(r) : "f"(x)); return r;
}
__device__ __forceinline__ float fex2_ap(float x) {
    float r; asm("ex2.approx.ftz.f32 %0, %1;" : "=f"(r) : "f"(x)); return r;
}
__device__ __forceinline__ float flg2_ap(float x) {
    float r; asm("lg2.approx.ftz.f32 %0, %1;" : "=f"(r) : "f"(x)); return r;
}

// shared dtype-sniffing nvalid computation (pure function of inputs)
__device__ __forceinline__ int compute_nvalid(const void* lenp, const void* stridep, int b) {
    long long s = 320;
    if (stridep) {
        long long v = *(const long long*)stridep;
        if (v > 0 && v < (1ll << 31)) s = v;
        else { int v32 = *(const int*)stridep; if (v32 > 0) s = v32; }
    }
    const long long* l64 = (const long long*)lenp;
    const int*       l32 = (const int*)lenp;
    bool is64 = true;
    for (int bb = 0; bb < Bc; bb++) {
        long long v = l64[bb];
        if (v < 0 || v >= (1ll << 31)) { is64 = false; break; }
    }
    long long L = is64 ? l64[b] : (long long)l32[b];
    long long nv = L / s;
    if (nv > Tc) nv = Tc;
    if (nv < 0) nv = 0;
    return (int)nv;
}

#define CP_ASYNC16(dst, src) \
    asm volatile("cp.async.cg.shared.global [%0], [%1], 16;" :: "r"(dst), "l"(src))
#define CP_COMMIT() asm volatile("cp.async.commit_group;")
#define CP_WAIT(n)  asm volatile("cp.async.wait_group %0;" :: "n"(n))

#define LDSM4(R, addr) \
    asm volatile("ldmatrix.sync.aligned.m8n8.x4.shared.b16 {%0,%1,%2,%3}, [%4];" \
        : "=r"((R)[0]), "=r"((R)[1]), "=r"((R)[2]), "=r"((R)[3]) : "r"(addr))

#define MMA_BF16(C, A, b0, b1) \
    asm volatile("mma.sync.aligned.m16n8k16.row.col.f32.bf16.bf16.f32 " \
        "{%0,%1,%2,%3}, {%4,%5,%6,%7}, {%8,%9}, {%0,%1,%2,%3};" \
        : "+f"((C)[0]), "+f"((C)[1]), "+f"((C)[2]), "+f"((C)[3]) \
        : "r"((A)[0]), "r"((A)[1]), "r"((A)[2]), "r"((A)[3]), "r"(b0), "r"(b1))

// ---------------- k_pre: fused prep(transpose+z2) / c2 / init, mask-skip ----------------
__global__ __launch_bounds__(256)
void k_pre(const float* __restrict__ feat, const float* __restrict__ cb,
           const void* lenp, const void* stridep) {
    const int blk = blockIdx.x;
    const int tid = threadIdx.x;
    if (blk < PREP_BLKS) {
        const int b  = blk / TTILES;
        const int t0 = (blk - b * TTILES) * 32;
        // mask-skip: tile fully beyond valid prefix does no work
        const int nv = compute_nvalid(lenp, stridep, b);
        if (t0 >= nv) return;

        __shared__ uint32_t tile[32][257];
        __shared__ float sz[32];
        const int tx = tid & 31, ty = tid >> 5;
        if (tid < 32) sz[tid] = 0.f;
        __syncthreads();
        const int t = t0 + tx;
        const bool tval = t < Tc;
        const float* src = feat + (size_t)b * Dc * Tc + t;
        float ssq = 0.f;
        #pragma unroll 8
        for (int j = 0; j < 32; j++) {
            int d = (j * 8 + ty) * 2;
            float v0 = tval ? src[(size_t)d * Tc] : 0.f;
            float v1 = tval ? src[(size_t)(d + 1) * Tc] : 0.f;
            ssq += v0 * v0 + v1 * v1;
            __nv_bfloat162 p = __floats2bfloat162_rn(-2.f * v0, -2.f * v1);
            tile[tx][d >> 1] = *(uint32_t*)&p;
        }
        atomicAdd(&sz[tx], ssq);
        __syncthreads();
        if (ty == 0 && tval) g_z2[b * Tc + t] = sz[tx];
        uint32_t* dst = (uint32_t*)&g_zt[(size_t)(b * Tc + t0) * Dc];
        #pragma unroll
        for (int r = 0; r < 32; r++) {
            if (t0 + r < Tc) dst[r * 256 + tid] = tile[r][tid];
        }
    } else {
        const int cblk = blk - PREP_BLKS;    // 0..511
        int zi = cblk * 256 + tid;
        if (zi < Nc) g_Z[zi] = 0.f;
        if (zi < Kc) g_cd[zi] = 0.f;
        if (cblk == 0 && tid < Bc) {
            g_nvalid[tid] = compute_nvalid(lenp, stridep, tid);
        }
        const int code = cblk * 8 + (tid >> 5);
        const int lane = tid & 31;
        const float* r = cb + (size_t)code * Dc;
        __nv_bfloat16* w = g_cbt + (size_t)code * Dc;
        float s = 0.f;
        #pragma unroll
        for (int it = 0; it < 4; it++) {
            int d = it * 128 + lane * 4;
            float4 v = *(const float4*)(r + d);
            s += v.x * v.x + v.y * v.y + v.z * v.z + v.w * v.w;
            __nv_bfloat162 p0 = __floats2bfloat162_rn(v.x, v.y);
            __nv_bfloat162 p1 = __floats2bfloat162_rn(v.z, v.w);
            *(uint2*)(w + d) = make_uint2(*(uint32_t*)&p0, *(uint32_t*)&p1);
        }
        #pragma unroll
        for (int o = 16; o; o >>= 1) s += __shfl_down_sync(0xffffffffu, s, o);
        if (lane == 0) g_c2[code] = s;
    }
}

// ---------------- cp.async stage issue ----------------
__device__ __forceinline__ void issue_stage(uint32_t sb, int kc, int n0, int k0, int tid) {
    uint32_t sbase = sb + (uint32_t)(kc % NSTG) * STAGE;
    int kcol = kc * 64;
    #pragma unroll
    for (int i = 0; i < 4; i++) {
        int id = i * 256 + tid;
        int row = id >> 3, ch = id & 7;
        const void* src = &g_zt[(size_t)(n0 + row) * Dc + kcol + ch * 8];
        uint32_t dst = sbase + swz((uint32_t)(row * 128 + ch * 16));
        CP_ASYNC16(dst, src);
    }
    #pragma unroll
    for (int i = 0; i < 4; i++) {
        int id = i * 256 + tid;
        int row = id >> 3, ch = id & 7;
        const void* src = &g_cbt[(size_t)(k0 + row) * Dc + kcol + ch * 8];
        uint32_t dst = sbase + 16384u + swz((uint32_t)(row * 128 + ch * 16));
        CP_ASYNC16(dst, src);
    }
    CP_COMMIT();
}

// ---------------- bf16 mma GEMM + fused softmax-numerator epilogue ----------------
// CTA 128x128, 8 warps in 2x4, warp tile 64x32. 3-stage cp.async, 2 CTAs/SM.
__global__ __launch_bounds__(256, 2)
void k_gemm_mma() {
    extern __shared__ __align__(1024) char smem[];
    const uint32_t sb = smem_u32(smem);
    const int tid  = threadIdx.x;
    const int warp = tid >> 5;
    const int lane = tid & 31;
    const int k0 = blockIdx.x * COLB;
    const int n0 = blockIdx.y * ROWB;

    // sync-free CTA skip: valid rows are a prefix of each batch
    {
        int b0 = n0 / Tc, t0 = n0 - b0 * Tc;
        bool any = (t0 < g_nvalid[b0]);
        if (!any && (t0 + ROWB > Tc) && (b0 + 1 < Bc)) any = (g_nvalid[b0 + 1] > 0);
        if (!any) return;
    }

    issue_stage(sb, 0, n0, k0, tid);
    issue_stage(sb, 1, n0, k0, tid);

    const int wr = warp >> 2;
    const int wc = warp & 3;
    const int g  = lane >> 3;
    const int lr = lane & 7;

    uint32_t aoff[4], boff[2];
    {
        int arow  = wr * 64 + (g & 1) * 8 + lr;
        int acolb = (g >> 1) * 16;
        #pragma unroll
        for (int mt = 0; mt < 4; mt++)
            aoff[mt] = swz((uint32_t)((arow + mt * 16) * 128 + acolb));
        int bcolb = (g & 1) * 16;
        #pragma unroll
        for (int p = 0; p < 2; p++) {
            int brow = wc * 32 + p * 16 + (g >> 1) * 8 + lr;
            boff[p] = 16384u + swz((uint32_t)(brow * 128 + bcolb));
        }
    }

    float acc[4][4][4];
    #pragma unroll
    for (int mt = 0; mt < 4; mt++)
        #pragma unroll
        for (int nt = 0; nt < 4; nt++)
            #pragma unroll
            for (int q = 0; q < 4; q++) acc[mt][nt][q] = 0.f;

    #pragma unroll 1
    for (int kc = 0; kc < NKCH; kc++) {
        if (kc < NKCH - 1) { CP_WAIT(1); } else { CP_WAIT(0); }
        __syncthreads();   // publishes stage kc; proves compute kc-1 done
        if (kc + 2 < NKCH) issue_stage(sb, kc + 2, n0, k0, tid);
        uint32_t sbase = sb + (uint32_t)(kc % NSTG) * STAGE;
        #pragma unroll
        for (int ks = 0; ks < 4; ks++) {
            const uint32_t kx = (uint32_t)(ks * 32);   // swz(off+kx)==swz(off)^kx
            uint32_t A[4][4], B[2][4];
            #pragma unroll
            for (int mt = 0; mt < 4; mt++) LDSM4(A[mt], sbase + (aoff[mt] ^ kx));
            #pragma unroll
            for (int p = 0; p < 2; p++)    LDSM4(B[p],  sbase + (boff[p] ^ kx));
            #pragma unroll
            for (int mt = 0; mt < 4; mt++)
                #pragma unroll
                for (int nt = 0; nt < 4; nt++)
                    MMA_BF16(acc[mt][nt], A[mt], B[nt >> 1][(nt & 1) * 2], B[nt >> 1][(nt & 1) * 2 + 1]);
        }
    }

    // ---- fused epilogue: w = ex2(-log2e * sqrt(max(z2 + c2 + acc, 1e-12))) ----
    const float NLOG2E = -1.4426950408889634f;
    const int rowq = lane >> 2;
    const int colp = (lane & 3) * 2;
    #pragma unroll
    for (int mt = 0; mt < 4; mt++) {
        int r0 = n0 + wr * 64 + mt * 16 + rowq;
        int r1 = r0 + 8;
        int b0i = r0 / Tc, t0i = r0 - b0i * Tc;
        int b1i = r1 / Tc, t1i = r1 - b1i * Tc;
        bool v0 = (r0 < Nc) && (t0i < g_nvalid[b0i]);
        bool v1 = (r1 < Nc) && (t1i < g_nvalid[b1i]);
        float z20 = v0 ? g_z2[r0] : 0.f;
        float z21 = v1 ? g_z2[r1] : 0.f;
        float rs0 = 0.f, rs1 = 0.f;
        #pragma unroll
        for (int nt = 0; nt < 4; nt++) {
            int col = k0 + wc * 32 + nt * 8 + colp;
            float2 c2 = *(const float2*)&g_c2[col];
            if (v0) {
                float d2a = fmaxf(z20 + c2.x + acc[mt][nt][0], 1e-12f);
                float d2b = fmaxf(z20 + c2.y + acc[mt][nt][1], 1e-12f);
                float w0 = fex2_ap(NLOG2E * fsqrt_ap(d2a));
                float w1 = fex2_ap(NLOG2E * fsqrt_ap(d2b));
                rs0 += w0 + w1;
                __nv_bfloat162 pk = __floats2bfloat162_rn(w0, w1);
                *(__nv_bfloat162*)&g_w[(size_t)r0 * Kc + col] = pk;
            }
            if (v1) {
                float d2a = fmaxf(z21 + c2.x + acc[mt][nt][2], 1e-12f);
                float d2b = fmaxf(z21 + c2.y + acc[mt][nt][3], 1e-12f);
                float w0 = fex2_ap(NLOG2E * fsqrt_ap(d2a));
                float w1 = fex2_ap(NLOG2E * fsqrt_ap(d2b));
                rs1 += w0 + w1;
                __nv_bfloat162 pk = __floats2bfloat162_rn(w0, w1);
                *(__nv_bfloat162*)&g_w[(size_t)r1 * Kc + col] = pk;
            }
        }
        rs0 += __shfl_xor_sync(0xffffffffu, rs0, 1);
        rs0 += __shfl_xor_sync(0xffffffffu, rs0, 2);
        rs1 += __shfl_xor_sync(0xffffffffu, rs1, 1);
        rs1 += __shfl_xor_sync(0xffffffffu, rs1, 2);
        if ((lane & 3) == 0) {
            if (v0) atomicAdd(&g_Z[r0], rs0);
            if (v1) atomicAdd(&g_Z[r1], rs1);
        }
    }
}

// ---------------- column reduce: uint4 loads, fused cd atomics ----------------
__global__ void k_colreduce() {
    const int grp = blockIdx.x * blockDim.x + threadIdx.x;   // 0..511 (uint4 group)
    const int chunk = blockIdx.y;                             // 0..319
    const int b  = chunk / CPB;
    const int t0 = (chunk - b * CPB) * RCHUNK;
    const int nv = g_nvalid[b];
    int tend = nv - t0;
    if (tend <= 0) return;
    if (tend > RCHUNK) tend = RCHUNK;
    float acc[8];
    #pragma unroll
    for (int j = 0; j < 8; j++) acc[j] = 0.f;
    int n = b * Tc + t0;
    const char* base = (const char*)g_w + (size_t)n * Kc * 2 + grp * 16;
    #pragma unroll 4
    for (int i = 0; i < tend; i++, n++, base += Kc * 2) {
        uint4 v = *(const uint4*)base;
        float iz = __fdividef(1.f, g_Z[n]);
        float2 f0 = __bfloat1622float2(*(const __nv_bfloat162*)&v.x);
        float2 f1 = __bfloat1622float2(*(const __nv_bfloat162*)&v.y);
        float2 f2 = __bfloat1622float2(*(const __nv_bfloat162*)&v.z);
        float2 f3 = __bfloat1622float2(*(const __nv_bfloat162*)&v.w);
        acc[0] += f0.x * iz; acc[1] += f0.y * iz;
        acc[2] += f1.x * iz; acc[3] += f1.y * iz;
        acc[4] += f2.x * iz; acc[5] += f2.y * iz;
        acc[6] += f3.x * iz; acc[7] += f3.y * iz;
    }
    #pragma unroll
    for (int j = 0; j < 8; j++) atomicAdd(&g_cd[grp * 8 + j], acc[j]);
}

// ---------------- final entropy (reads 16KB g_cd) ----------------
__device__ __forceinline__ float blockSum(float v) {
    __shared__ float sh[32];
    int lane = threadIdx.x & 31, w = threadIdx.x >> 5;
    #pragma unroll
    for (int o = 16; o; o >>= 1) v += __shfl_down_sync(0xffffffffu, v, o);
    if (!lane) sh[w] = v;
    __syncthreads();
    float r = 0.f;
    if (w == 0) {
        r = (lane < (blockDim.x >> 5)) ? sh[lane] : 0.f;
        #pragma unroll
        for (int o = 16; o; o >>= 1) r += __shfl_down_sync(0xffffffffu, r, o);
        if (!lane) sh[0] = r;
    }
    __syncthreads();
    float out = sh[0];
    __syncthreads();
    return out;
}

__global__ void k_final(float* out) {
    const int tid = threadIdx.x;   // 1024
    const float LN2 = 0.6931471805599453f;
    float cd[4];
    #pragma unroll
    for (int j = 0; j < 4; j++) cd[j] = g_cd[tid + j * 1024];
    float tot = (cd[0] + cd[1]) + (cd[2] + cd[3]);
    float S = blockSum(tot);
    float denom = S + 1e-8f;
    float e = 0.f;
    #pragma unroll
    for (int j = 0; j < 4; j++) {
        float p = cd[j] / denom;
        e += p * (flg2_ap(p + 1e-8f) * LN2);   // log(x) = lg2(x)*ln2
    }
    float E = blockSum(e);
    if (tid == 0) out[0] = 1.f + E / (flg2_ap((float)Kc) * LN2);
}

// ---------------- launch ----------------
extern "C" void kernel_launch(void* const* d_in, const int* in_sizes, int n_in,
                              void* d_out, int out_size) {
    const float* feat = (const float*)d_in[0];
    const float* cb   = (const float*)d_in[1];
    const void*  lenp = d_in[2];
    const void*  stridep = (n_in > 3) ? d_in[3] : nullptr;

    cudaFuncSetAttribute(k_gemm_mma, cudaFuncAttributeMaxDynamicSharedMemorySize, SMEM_BYTES);

    k_pre<<<PREP_BLKS + Kc / 8, 256>>>(feat, cb, lenp, stridep);   // 1264 blocks

    dim3 gg(NCB, NRB);                       // 32 x 188
    k_gemm_mma<<<gg, 256, SMEM_BYTES>>>();

    dim3 gr(Kc / 2048, NCHUNKS);             // 2 x 320 (uint4 groups)
    k_colreduce<<<gr, 256>>>();
    k_final<<<1, 1024>>>((float*)d_out);
    (void)in_sizes; (void)out_size;
}

// round 17
// speedup vs baseline: 1.1669x; 1.0422x over previous
#include <cuda_runtime.h>
#include <cuda_bf16.h>
#include <cstdint>
#include <cstddef>

// ---------------- problem constants ----------------
static constexpr int Bc = 16;
static constexpr int Dc = 512;
static constexpr int Tc = 1500;
static constexpr int Nc = Bc * Tc;              // 24000
static constexpr int Kc = 4096;
static constexpr int ROWB = 128;                // CTA row tile
static constexpr int COLB = 128;                // CTA col tile
static constexpr int NRB  = (Nc + ROWB - 1) / ROWB;   // 188
static constexpr int NPAD = NRB * ROWB;         // 24064
static constexpr int NCB  = Kc / COLB;          // 32
static constexpr int NKCH = 8;                  // 512 / 64
static constexpr int CPB    = 20;               // chunks per batch (best)
static constexpr int RCHUNK = Tc / CPB;         // 75 rows, batch-aligned
static constexpr int NCHUNKS = Bc * CPB;        // 320
static constexpr int STAGE = 32768;             // A 16KB + B 16KB per stage
static constexpr int NSTG  = 3;                 // 3-stage pipeline
static constexpr int SMEM_BYTES = NSTG * STAGE; // 98304 dynamic; +1KB static -> 2 CTAs/SM
static constexpr int TTILES = 47;               // ceil(1500/32)
static constexpr int PREP_BLKS = TTILES * Bc;   // 752

// ---------------- device scratch ----------------
// Device globals are zero-initialized at load; g_zt pad rows (Nc..NPAD) are
// never written and stay zero. Masked-row tiles of g_zt may hold stale values
// across graph replays: inputs are identical per replay, and masked rows'
// GEMM results are discarded in the epilogue, so output stays deterministic.
__device__ __nv_bfloat16 g_w[(size_t)NPAD * Kc];     // exp(-dist) numerators
__device__ __nv_bfloat16 g_zt[(size_t)NPAD * Dc];    // -2*z bf16 [N][512]
__device__ __nv_bfloat16 g_cbt[(size_t)Kc * Dc];     // bf16 codebook [K][512]
__device__ float g_Z[Nc];
__device__ float g_z2[Nc];
__device__ float g_c2[Kc];
__device__ int   g_nvalid[Bc];
__device__ float g_cd[Kc];

// ---------------- helpers ----------------
__device__ __forceinline__ uint32_t smem_u32(const void* p) {
    uint32_t a;
    asm("{ .reg .u64 t; cvta.to.shared.u64 t, %1; cvt.u32.u64 %0, t; }" : "=r"(a) : "l"(p));
    return a;
}
__device__ __forceinline__ uint32_t swz(uint32_t off) { return off ^ ((off >> 3) & 0x70); }
__device__ __forceinline__ float fsqrt_ap(float x) {
    float r; asm("sqrt.approx.ftz.f32 %0, %1;" : "=f"(r) : "f"(x)); return r;
}
__device__ __forceinline__ float fex2_ap(float x) {
    float r; asm("ex2.approx.ftz.f32 %0, %1;" : "=f"(r) : "f"(x)); return r;
}
__device__ __forceinline__ float flg2_ap(float x) {
    float r; asm("lg2.approx.ftz.f32 %0, %1;" : "=f"(r) : "f"(x)); return r;
}

// shared dtype-sniffing nvalid computation (pure function of inputs)
__device__ __forceinline__ int compute_nvalid(const void* lenp, const void* stridep, int b) {
    long long s = 320;
    if (stridep) {
        long long v = *(const long long*)stridep;
        if (v > 0 && v < (1ll << 31)) s = v;
        else { int v32 = *(const int*)stridep; if (v32 > 0) s = v32; }
    }
    const long long* l64 = (const long long*)lenp;
    const int*       l32 = (const int*)lenp;
    bool is64 = true;
    for (int bb = 0; bb < Bc; bb++) {
        long long v = l64[bb];
        if (v < 0 || v >= (1ll << 31)) { is64 = false; break; }
    }
    long long L = is64 ? l64[b] : (long long)l32[b];
    long long nv = L / s;
    if (nv > Tc) nv = Tc;
    if (nv < 0) nv = 0;
    return (int)nv;
}

#define CP_ASYNC16(dst, src) \
    asm volatile("cp.async.cg.shared.global [%0], [%1], 16;" :: "r"(dst), "l"(src))
#define CP_COMMIT() asm volatile("cp.async.commit_group;")
#define CP_WAIT(n)  asm volatile("cp.async.wait_group %0;" :: "n"(n))

#define LDSM4(R, addr) \
    asm volatile("ldmatrix.sync.aligned.m8n8.x4.shared.b16 {%0,%1,%2,%3}, [%4];" \
        : "=r"((R)[0]), "=r"((R)[1]), "=r"((R)[2]), "=r"((R)[3]) : "r"(addr))

#define MMA_BF16(C, A, b0, b1) \
    asm volatile("mma.sync.aligned.m16n8k16.row.col.f32.bf16.bf16.f32 " \
        "{%0,%1,%2,%3}, {%4,%5,%6,%7}, {%8,%9}, {%0,%1,%2,%3};" \
        : "+f"((C)[0]), "+f"((C)[1]), "+f"((C)[2]), "+f"((C)[3]) \
        : "r"((A)[0]), "r"((A)[1]), "r"((A)[2]), "r"((A)[3]), "r"(b0), "r"(b1))

// ---------------- k_pre: fused prep(transpose+z2) / c2 / init, mask-skip ----------------
__global__ __launch_bounds__(256)
void k_pre(const float* __restrict__ feat, const float* __restrict__ cb,
           const void* lenp, const void* stridep) {
    const int blk = blockIdx.x;
    const int tid = threadIdx.x;
    if (blk < PREP_BLKS) {
        const int b  = blk / TTILES;
        const int t0 = (blk - b * TTILES) * 32;
        // mask-skip: tile fully beyond valid prefix does no work
        const int nv = compute_nvalid(lenp, stridep, b);
        if (t0 >= nv) return;

        __shared__ uint32_t tile[32][257];
        __shared__ float sz[32];
        const int tx = tid & 31, ty = tid >> 5;
        if (tid < 32) sz[tid] = 0.f;
        __syncthreads();
        const int t = t0 + tx;
        const bool tval = t < Tc;
        const float* src = feat + (size_t)b * Dc * Tc + t;
        float ssq = 0.f;
        #pragma unroll 8
        for (int j = 0; j < 32; j++) {
            int d = (j * 8 + ty) * 2;
            float v0 = tval ? src[(size_t)d * Tc] : 0.f;
            float v1 = tval ? src[(size_t)(d + 1) * Tc] : 0.f;
            ssq += v0 * v0 + v1 * v1;
            __nv_bfloat162 p = __floats2bfloat162_rn(-2.f * v0, -2.f * v1);
            tile[tx][d >> 1] = *(uint32_t*)&p;
        }
        atomicAdd(&sz[tx], ssq);
        __syncthreads();
        if (ty == 0 && tval) g_z2[b * Tc + t] = sz[tx];
        uint32_t* dst = (uint32_t*)&g_zt[(size_t)(b * Tc + t0) * Dc];
        #pragma unroll
        for (int r = 0; r < 32; r++) {
            if (t0 + r < Tc) dst[r * 256 + tid] = tile[r][tid];
        }
    } else {
        const int cblk = blk - PREP_BLKS;    // 0..511
        int zi = cblk * 256 + tid;
        if (zi < Nc) g_Z[zi] = 0.f;
        if (zi < Kc) g_cd[zi] = 0.f;
        if (cblk == 0 && tid < Bc) {
            g_nvalid[tid] = compute_nvalid(lenp, stridep, tid);
        }
        const int code = cblk * 8 + (tid >> 5);
        const int lane = tid & 31;
        const float* r = cb + (size_t)code * Dc;
        __nv_bfloat16* w = g_cbt + (size_t)code * Dc;
        float s = 0.f;
        #pragma unroll
        for (int it = 0; it < 4; it++) {
            int d = it * 128 + lane * 4;
            float4 v = *(const float4*)(r + d);
            s += v.x * v.x + v.y * v.y + v.z * v.z + v.w * v.w;
            __nv_bfloat162 p0 = __floats2bfloat162_rn(v.x, v.y);
            __nv_bfloat162 p1 = __floats2bfloat162_rn(v.z, v.w);
            *(uint2*)(w + d) = make_uint2(*(uint32_t*)&p0, *(uint32_t*)&p1);
        }
        #pragma unroll
        for (int o = 16; o; o >>= 1) s += __shfl_down_sync(0xffffffffu, s, o);
        if (lane == 0) g_c2[code] = s;
    }
}

// ---------------- cp.async stage issue ----------------
__device__ __forceinline__ void issue_stage(uint32_t sb, int kc, int n0, int k0, int tid) {
    uint32_t sbase = sb + (uint32_t)(kc % NSTG) * STAGE;
    int kcol = kc * 64;
    #pragma unroll
    for (int i = 0; i < 4; i++) {
        int id = i * 256 + tid;
        int row = id >> 3, ch = id & 7;
        const void* src = &g_zt[(size_t)(n0 + row) * Dc + kcol + ch * 8];
        uint32_t dst = sbase + swz((uint32_t)(row * 128 + ch * 16));
        CP_ASYNC16(dst, src);
    }
    #pragma unroll
    for (int i = 0; i < 4; i++) {
        int id = i * 256 + tid;
        int row = id >> 3, ch = id & 7;
        const void* src = &g_cbt[(size_t)(k0 + row) * Dc + kcol + ch * 8];
        uint32_t dst = sbase + 16384u + swz((uint32_t)(row * 128 + ch * 16));
        CP_ASYNC16(dst, src);
    }
    CP_COMMIT();
}

// ---------------- bf16 mma GEMM + fused softmax-numerator epilogue ----------------
// CTA 128x128, 8 warps in 2x4, warp tile 64x32. 3-stage cp.async, 2 CTAs/SM.
// Epilogue operands (c2 slice, z2 slice) prefetched into smem during mainloop.
__global__ __launch_bounds__(256, 2)
void k_gemm_mma() {
    extern __shared__ __align__(1024) char smem[];
    __shared__ float sc2[128];   // c2[k0 .. k0+127]
    __shared__ float sz2[128];   // z2[n0 .. n0+127] (stale/0 for invalid rows; unused)
    const uint32_t sb = smem_u32(smem);
    const int tid  = threadIdx.x;
    const int warp = tid >> 5;
    const int lane = tid & 31;
    const int k0 = blockIdx.x * COLB;
    const int n0 = blockIdx.y * ROWB;

    // sync-free CTA skip: valid rows are a prefix of each batch
    {
        int b0 = n0 / Tc, t0 = n0 - b0 * Tc;
        bool any = (t0 < g_nvalid[b0]);
        if (!any && (t0 + ROWB > Tc) && (b0 + 1 < Bc)) any = (g_nvalid[b0 + 1] > 0);
        if (!any) return;
    }

    issue_stage(sb, 0, n0, k0, tid);

    // epilogue-operand prefetch: lands during the mainloop, read from smem later
    if (tid < 128) {
        sc2[tid] = g_c2[k0 + tid];
        int n = n0 + tid;
        sz2[tid] = (n < Nc) ? g_z2[n] : 0.f;
    }

    issue_stage(sb, 1, n0, k0, tid);

    const int wr = warp >> 2;
    const int wc = warp & 3;
    const int g  = lane >> 3;
    const int lr = lane & 7;

    uint32_t aoff[4], boff[2];
    {
        int arow  = wr * 64 + (g & 1) * 8 + lr;
        int acolb = (g >> 1) * 16;
        #pragma unroll
        for (int mt = 0; mt < 4; mt++)
            aoff[mt] = swz((uint32_t)((arow + mt * 16) * 128 + acolb));
        int bcolb = (g & 1) * 16;
        #pragma unroll
        for (int p = 0; p < 2; p++) {
            int brow = wc * 32 + p * 16 + (g >> 1) * 8 + lr;
            boff[p] = 16384u + swz((uint32_t)(brow * 128 + bcolb));
        }
    }

    float acc[4][4][4];
    #pragma unroll
    for (int mt = 0; mt < 4; mt++)
        #pragma unroll
        for (int nt = 0; nt < 4; nt++)
            #pragma unroll
            for (int q = 0; q < 4; q++) acc[mt][nt][q] = 0.f;

    #pragma unroll 1
    for (int kc = 0; kc < NKCH; kc++) {
        if (kc < NKCH - 1) { CP_WAIT(1); } else { CP_WAIT(0); }
        __syncthreads();   // publishes stage kc (and, on kc=0, the sc2/sz2 prefetch)
        if (kc + 2 < NKCH) issue_stage(sb, kc + 2, n0, k0, tid);
        uint32_t sbase = sb + (uint32_t)(kc % NSTG) * STAGE;
        #pragma unroll
        for (int ks = 0; ks < 4; ks++) {
            const uint32_t kx = (uint32_t)(ks * 32);   // swz(off+kx)==swz(off)^kx
            uint32_t A[4][4], B[2][4];
            #pragma unroll
            for (int mt = 0; mt < 4; mt++) LDSM4(A[mt], sbase + (aoff[mt] ^ kx));
            #pragma unroll
            for (int p = 0; p < 2; p++)    LDSM4(B[p],  sbase + (boff[p] ^ kx));
            #pragma unroll
            for (int mt = 0; mt < 4; mt++)
                #pragma unroll
                for (int nt = 0; nt < 4; nt++)
                    MMA_BF16(acc[mt][nt], A[mt], B[nt >> 1][(nt & 1) * 2], B[nt >> 1][(nt & 1) * 2 + 1]);
        }
    }

    // ---- fused epilogue: w = ex2(-log2e * sqrt(max(z2 + c2 + acc, 1e-12))) ----
    const float NLOG2E = -1.4426950408889634f;
    const int rowq = lane >> 2;
    const int colp = (lane & 3) * 2;
    #pragma unroll
    for (int mt = 0; mt < 4; mt++) {
        int lr0 = wr * 64 + mt * 16 + rowq;        // local row in [0,128)
        int r0 = n0 + lr0;
        int r1 = r0 + 8;
        int b0i = r0 / Tc, t0i = r0 - b0i * Tc;
        int b1i = r1 / Tc, t1i = r1 - b1i * Tc;
        bool v0 = (r0 < Nc) && (t0i < g_nvalid[b0i]);
        bool v1 = (r1 < Nc) && (t1i < g_nvalid[b1i]);
        float z20 = sz2[lr0];
        float z21 = sz2[lr0 + 8];
        float rs0 = 0.f, rs1 = 0.f;
        #pragma unroll
        for (int nt = 0; nt < 4; nt++) {
            int lcol = wc * 32 + nt * 8 + colp;    // local col in [0,128)
            float2 c2 = *(const float2*)&sc2[lcol];
            int col = k0 + lcol;
            if (v0) {
                float d2a = fmaxf(z20 + c2.x + acc[mt][nt][0], 1e-12f);
                float d2b = fmaxf(z20 + c2.y + acc[mt][nt][1], 1e-12f);
                float w0 = fex2_ap(NLOG2E * fsqrt_ap(d2a));
                float w1 = fex2_ap(NLOG2E * fsqrt_ap(d2b));
                rs0 += w0 + w1;
                __nv_bfloat162 pk = __floats2bfloat162_rn(w0, w1);
                *(__nv_bfloat162*)&g_w[(size_t)r0 * Kc + col] = pk;
            }
            if (v1) {
                float d2a = fmaxf(z21 + c2.x + acc[mt][nt][2], 1e-12f);
                float d2b = fmaxf(z21 + c2.y + acc[mt][nt][3], 1e-12f);
                float w0 = fex2_ap(NLOG2E * fsqrt_ap(d2a));
                float w1 = fex2_ap(NLOG2E * fsqrt_ap(d2b));
                rs1 += w0 + w1;
                __nv_bfloat162 pk = __floats2bfloat162_rn(w0, w1);
                *(__nv_bfloat162*)&g_w[(size_t)r1 * Kc + col] = pk;
            }
        }
        rs0 += __shfl_xor_sync(0xffffffffu, rs0, 1);
        rs0 += __shfl_xor_sync(0xffffffffu, rs0, 2);
        rs1 += __shfl_xor_sync(0xffffffffu, rs1, 1);
        rs1 += __shfl_xor_sync(0xffffffffu, rs1, 2);
        if ((lane & 3) == 0) {
            if (v0) atomicAdd(&g_Z[r0], rs0);
            if (v1) atomicAdd(&g_Z[r1], rs1);
        }
    }
}

// ---------------- column reduce: uint4 loads, fused cd atomics ----------------
__global__ void k_colreduce() {
    const int grp = blockIdx.x * blockDim.x + threadIdx.x;   // 0..511 (uint4 group)
    const int chunk = blockIdx.y;                             // 0..319
    const int b  = chunk / CPB;
    const int t0 = (chunk - b * CPB) * RCHUNK;
    const int nv = g_nvalid[b];
    int tend = nv - t0;
    if (tend <= 0) return;
    if (tend > RCHUNK) tend = RCHUNK;
    float acc[8];
    #pragma unroll
    for (int j = 0; j < 8; j++) acc[j] = 0.f;
    int n = b * Tc + t0;
    const char* base = (const char*)g_w + (size_t)n * Kc * 2 + grp * 16;
    #pragma unroll 4
    for (int i = 0; i < tend; i++, n++, base += Kc * 2) {
        uint4 v = *(const uint4*)base;
        float iz = __fdividef(1.f, g_Z[n]);
        float2 f0 = __bfloat1622float2(*(const __nv_bfloat162*)&v.x);
        float2 f1 = __bfloat1622float2(*(const __nv_bfloat162*)&v.y);
        float2 f2 = __bfloat1622float2(*(const __nv_bfloat162*)&v.z);
        float2 f3 = __bfloat1622float2(*(const __nv_bfloat162*)&v.w);
        acc[0] += f0.x * iz; acc[1] += f0.y * iz;
        acc[2] += f1.x * iz; acc[3] += f1.y * iz;
        acc[4] += f2.x * iz; acc[5] += f2.y * iz;
        acc[6] += f3.x * iz; acc[7] += f3.y * iz;
    }
    #pragma unroll
    for (int j = 0; j < 8; j++) atomicAdd(&g_cd[grp * 8 + j], acc[j]);
}

// ---------------- final entropy (reads 16KB g_cd) ----------------
__device__ __forceinline__ float blockSum(float v) {
    __shared__ float sh[32];
    int lane = threadIdx.x & 31, w = threadIdx.x >> 5;
    #pragma unroll
    for (int o = 16; o; o >>= 1) v += __shfl_down_sync(0xffffffffu, v, o);
    if (!lane) sh[w] = v;
    __syncthreads();
    float r = 0.f;
    if (w == 0) {
        r = (lane < (blockDim.x >> 5)) ? sh[lane] : 0.f;
        #pragma unroll
        for (int o = 16; o; o >>= 1) r += __shfl_down_sync(0xffffffffu, r, o);
        if (!lane) sh[0] = r;
    }
    __syncthreads();
    float out = sh[0];
    __syncthreads();
    return out;
}

__global__ void k_final(float* out) {
    const int tid = threadIdx.x;   // 1024
    const float LN2 = 0.6931471805599453f;
    float cd[4];
    #pragma unroll
    for (int j = 0; j < 4; j++) cd[j] = g_cd[tid + j * 1024];
    float tot = (cd[0] + cd[1]) + (cd[2] + cd[3]);
    float S = blockSum(tot);
    float denom = S + 1e-8f;
    float e = 0.f;
    #pragma unroll
    for (int j = 0; j < 4; j++) {
        float p = cd[j] / denom;
        e += p * (flg2_ap(p + 1e-8f) * LN2);   // log(x) = lg2(x)*ln2
    }
    float E = blockSum(e);
    if (tid == 0) out[0] = 1.f + E / (flg2_ap((float)Kc) * LN2);
}

// ---------------- launch ----------------
extern "C" void kernel_launch(void* const* d_in, const int* in_sizes, int n_in,
                              void* d_out, int out_size) {
    const float* feat = (const float*)d_in[0];
    const float* cb   = (const float*)d_in[1];
    const void*  lenp = d_in[2];
    const void*  stridep = (n_in > 3) ? d_in[3] : nullptr;

    cudaFuncSetAttribute(k_gemm_mma, cudaFuncAttributeMaxDynamicSharedMemorySize, SMEM_BYTES);

    k_pre<<<PREP_BLKS + Kc / 8, 256>>>(feat, cb, lenp, stridep);   // 1264 blocks

    dim3 gg(NCB, NRB);                       // 32 x 188
    k_gemm_mma<<<gg, 256, SMEM_BYTES>>>();

    dim3 gr(Kc / 2048, NCHUNKS);             // 2 x 320 (uint4 groups)
    k_colreduce<<<gr, 256>>>();
    k_final<<<1, 1024>>>((float*)d_out);
    (void)in_sizes; (void)out_size;
}